// round 14
// baseline (speedup 1.0000x reference)
#include <cuda_runtime.h>
#include <stdint.h>
#include <math_constants.h>

// ProbSparse attention (Informer) — B=4, L=2048, H=8, D=64, U_part=u=40.
// Layout of all tensors: (B, L, H, D) row-major.

#define BB 4
#define LL 2048
#define HH 8
#define DD 64
#define UU 40
#define SS 40
#define BH (BB*HH)       // 32
#define NCHB 4           // key chunks for sampled-score bucketing
#define CKEY 512         // keys per bucket chunk
#define CSH  9           // log2(CKEY)
#define NCH 16           // key chunks for split-K attention
#define CH  128
#define SCALE 0.125f

__device__ __align__(16) uint16_t g_cnt16[NCHB*LL];
__device__ __align__(16) uint16_t g_pairs2[NCHB*LL*SS];   // [c][l][<=40]
__device__ __align__(16) float    g_pM[NCHB*BH*LL];
__device__ __align__(16) float    g_pS[NCHB*BH*LL];
__device__ __align__(16) int      g_Mtop[BH*UU];
__device__ __align__(16) float    g_Vmean[BH*DD];
__device__ __align__(16) float    g_pm[BH*UU*NCH];
__device__ __align__(16) float    g_ps[BH*UU*NCH];
__device__ __align__(16) float    g_pa[BH*UU*NCH*DD];

// ---------------------------------------------------------------------------
// Threefry-2x32-20, constexpr-evaluable.
// ---------------------------------------------------------------------------
__host__ __device__ constexpr uint64_t tf2x32(uint32_t k0, uint32_t k1,
                                              uint32_t c0, uint32_t c1) {
    uint32_t ks0 = k0, ks1 = k1, ks2 = k0 ^ k1 ^ 0x1BD11BDAu;
    uint32_t x0 = c0 + ks0, x1 = c1 + ks1;
    const int rotA[4] = {13, 15, 26, 6};
    const int rotB[4] = {17, 29, 16, 24};
    for (int g = 0; g < 5; g++) {
        const int* rot = (g & 1) ? rotB : rotA;
        for (int r = 0; r < 4; r++) {
            x0 += x1;
            x1 = (x1 << rot[r]) | (x1 >> (32 - rot[r]));
            x1 ^= x0;
        }
        uint32_t inj0 = 0, inj1 = 0;
        switch (g) {
            case 0: inj0 = ks1; inj1 = ks2 + 1u; break;
            case 1: inj0 = ks2; inj1 = ks0 + 2u; break;
            case 2: inj0 = ks0; inj1 = ks1 + 3u; break;
            case 3: inj0 = ks1; inj1 = ks2 + 4u; break;
            case 4: inj0 = ks2; inj1 = ks0 + 5u; break;
        }
        x0 += inj0; x1 += inj1;
    }
    return ((uint64_t)x0 << 32) | (uint64_t)x1;
}

constexpr uint64_t K2PAIR = tf2x32(0u, 42u, 0u, 1u);
#define K2_HI ((uint32_t)(K2PAIR >> 32))
#define K2_LO ((uint32_t)(K2PAIR & 0xffffffffu))

// ---------------------------------------------------------------------------
// K0 (side stream): zero g_Vmean.
// ---------------------------------------------------------------------------
__global__ void k_zero() {
    int i = blockIdx.x * 1024 + threadIdx.x;
    g_Vmean[i] = 0.f;
}

// ---------------------------------------------------------------------------
// K1 (fused rng+count+rank): one thread per query row l.
// ---------------------------------------------------------------------------
__device__ __forceinline__ uint32_t tf_fold(uint32_t c1v) {
    uint64_t y = tf2x32(K2_HI, K2_LO, 0u, c1v);
    return (uint32_t)(y >> 32) ^ (uint32_t)(y & 0xffffffffu);
}

__global__ void k_prep() {
    int l = blockIdx.x * 64 + threadIdx.x;
    int idx[SS];
#pragma unroll 1
    for (int s = 0; s < SS; s += 2) {
        uint32_t b0 = tf_fold((uint32_t)(l * SS + s));
        uint32_t b1 = tf_fold((uint32_t)(l * SS + s + 1));
        idx[s]     = (int)(b0 & (LL - 1));
        idx[s + 1] = (int)(b1 & (LL - 1));
    }
    int c0 = 0, c1 = 0, c2 = 0, c3 = 0;
#pragma unroll
    for (int s = 0; s < SS; s++) {
        int v = idx[s];
        int c = v >> CSH;
        uint16_t kl = (uint16_t)(v & (CKEY - 1));
        int r;
        if      (c == 0) r = c0++;
        else if (c == 1) r = c1++;
        else if (c == 2) r = c2++;
        else             r = c3++;
        g_pairs2[(c * LL + l) * SS + r] = kl;
    }
    g_cnt16[0 * LL + l] = (uint16_t)c0;
    g_cnt16[1 * LL + l] = (uint16_t)c1;
    g_cnt16[2 * LL + l] = (uint16_t)c2;
    g_cnt16[3 * LL + l] = (uint16_t)c3;
}

// ---------------------------------------------------------------------------
// K2: sampled-score partials (PROVEN R10 variant). Block = (bh, chunk of 512
// keys) -> 128 blocks, 1024 threads (32 warps), 132KB smem. Conflict-free
// octet LDS scheme.
// ---------------------------------------------------------------------------
#define SMP_SH_BYTES (CKEY*DD*4 + LL*2)

__global__ void __launch_bounds__(1024, 1) k_sampleM4(const float* __restrict__ Q,
                                                      const float* __restrict__ K) {
    int c  = blockIdx.x & (NCHB - 1);
    int bh = blockIdx.x >> 2;
    int b = bh >> 3, h = bh & 7;

    extern __shared__ float sk[];                    // [512][64]
    uint16_t* scnt = (uint16_t*)(sk + CKEY * DD);    // [2048]

    const float* Kc = K + ((size_t)(b * LL + c * CKEY) * HH + h) * DD;
    for (int i = threadIdx.x; i < CKEY * (DD / 4); i += 1024) {
        int r = i >> 4, q4 = i & 15;
        float4 v = __ldcg((const float4*)(Kc + (size_t)r * (HH * DD) + q4 * 4));
        *(float4*)(sk + r * DD + q4 * 4) = v;
    }
    for (int i = threadIdx.x; i < LL; i += 1024)
        scnt[i] = g_cnt16[c * LL + i];
    __syncthreads();

    int lane = threadIdx.x & 31, wid = threadIdx.x >> 5;
    int oct = lane >> 3;           // sample slot 0..3
    int oj  = lane & 7;            // position within octet

    for (int l = wid; l < LL; l += 32) {
        int cnt = (int)scnt[l];
        const float* qrow = Q + ((size_t)(b * LL + l) * HH + h) * DD;
        float4 qa = __ldcg((const float4*)(qrow + oj * 4));
        float4 qb = __ldcg((const float4*)(qrow + 32 + oj * 4));
        const uint16_t* pr = g_pairs2 + (c * LL + l) * SS;
        int pa = (lane < cnt) ? (int)pr[lane] : 0;
        int pb = (lane + 32 < cnt) ? (int)pr[lane + 32] : 0;

        float mx = -CUDART_INF_F, sm = 0.f;
        for (int t0 = 0; t0 < cnt; t0 += 4) {
            int src = t0 + oct;
            int kloc = (t0 < 32)
                     ? __shfl_sync(0xffffffffu, pa, src & 31)
                     : __shfl_sync(0xffffffffu, pb, src - 32);
            bool valid = src < cnt;
            const float* krow = sk + kloc * DD;
            float4 ka = *(const float4*)(krow + oj * 4);
            float4 kb = *(const float4*)(krow + 32 + oj * 4);
            float p = qa.x * ka.x + qa.y * ka.y + qa.z * ka.z + qa.w * ka.w
                    + qb.x * kb.x + qb.y * kb.y + qb.z * kb.z + qb.w * kb.w;
            p += __shfl_xor_sync(0xffffffffu, p, 1);
            p += __shfl_xor_sync(0xffffffffu, p, 2);
            p += __shfl_xor_sync(0xffffffffu, p, 4);
            if (valid) { mx = fmaxf(mx, p); sm += p; }
        }
        mx = fmaxf(mx, __shfl_xor_sync(0xffffffffu, mx, 8));
        mx = fmaxf(mx, __shfl_xor_sync(0xffffffffu, mx, 16));
        sm += __shfl_xor_sync(0xffffffffu, sm, 8);
        sm += __shfl_xor_sync(0xffffffffu, sm, 16);
        if (lane == 0) {
            g_pM[(c * BH + bh) * LL + l] = mx;
            g_pS[(c * BH + bh) * LL + l] = sm;
        }
    }
}

// ---------------------------------------------------------------------------
// K3: merge 4 chunk partials -> M, then exact top-40 per (b,h) via bitonic
// sort of (value,index), comparator (v desc, idx asc). 1024 threads.
// ---------------------------------------------------------------------------
__global__ void k_topk() {
    int bh = blockIdx.x;
    __shared__ float sv[LL];
    __shared__ int   si[LL];
    int t = threadIdx.x;
    for (int i = t; i < LL; i += 1024) {
        float mm = -CUDART_INF_F, s = 0.f;
#pragma unroll
        for (int c = 0; c < NCHB; c++) {
            mm = fmaxf(mm, g_pM[(c * BH + bh) * LL + i]);
            s += g_pS[(c * BH + bh) * LL + i];
        }
        sv[i] = mm - s * (1.0f / (float)LL);
        si[i] = i;
    }
    __syncthreads();
    for (int k = 2; k <= LL; k <<= 1) {
        for (int j = k >> 1; j > 0; j >>= 1) {
            for (int i = t; i < LL; i += 1024) {
                int p = i ^ j;
                if (p > i) {
                    bool asc = (i & k) == 0;
                    float va = sv[i], vp = sv[p];
                    int   ia = si[i], ip = si[p];
                    bool pre = (vp > va) || (vp == va && ip < ia);
                    if (asc == pre) {
                        sv[i] = vp; sv[p] = va;
                        si[i] = ip; si[p] = ia;
                    }
                }
            }
            __syncthreads();
        }
    }
    if (t < UU) g_Mtop[bh * UU + t] = si[t];
}

// ---------------------------------------------------------------------------
// K4: V_mean partials; 1024 blocks (bh x 32 L-chunks of 64), atomicAdd merge.
// ---------------------------------------------------------------------------
__global__ void k_vmean(const float* __restrict__ V) {
    int blk = blockIdx.x;
    int bh = blk >> 5, chn = blk & 31;
    int b = bh >> 3, h = bh & 7;
    int t = threadIdx.x;
    int d = t & 63, sub = t >> 6;
    float s = 0.f;
#pragma unroll 16
    for (int i = 0; i < 16; i++) {
        int l = chn * 64 + sub + i * 4;
        s += V[(((size_t)(b * LL + l)) * HH + h) * DD + d];
    }
    __shared__ float red[256];
    red[t] = s;
    __syncthreads();
    if (t < 64) {
        float tot = red[t] + red[t + 64] + red[t + 128] + red[t + 192];
        atomicAdd(&g_Vmean[bh * DD + t], tot * (1.0f / (float)LL));
    }
}

// ---------------------------------------------------------------------------
// K5: out[b,l,h,:] = V_mean[b,h,:] for all l.
// ---------------------------------------------------------------------------
__global__ void k_fill(float* __restrict__ out) {
    int i = blockIdx.x * blockDim.x + threadIdx.x;
    if (i >= BB * LL * HH * (DD / 4)) return;
    int q4  = i & 15;
    int row = i >> 4;
    int h = row & 7;
    int b = row >> 14;
    float4 vm = reinterpret_cast<const float4*>(g_Vmean)[((b << 3) + h) * (DD / 4) + q4];
    reinterpret_cast<float4*>(out)[i] = vm;
}

// ---------------------------------------------------------------------------
// K6a: split-K attention partials. Block = (b,h, key-chunk of 128), 256 thr.
// ---------------------------------------------------------------------------
#define QS_PITCH 66
#define KS_PITCH 66
#define S_PITCH  130
#define SH_FLOATS (UU*QS_PITCH + CH*KS_PITCH + CH*KS_PITCH + UU*S_PITCH)
#define SH_BYTES  (SH_FLOATS*4 + UU*4)

__global__ void k_attn_part(const float* __restrict__ Q, const float* __restrict__ K,
                            const float* __restrict__ V) {
    int ch = blockIdx.x & (NCH - 1);
    int bh = blockIdx.x >> 4;
    int b = bh >> 3, h = bh & 7;
    int t = threadIdx.x;

    extern __shared__ float sh[];
    float* Qs = sh;                          // [40][66]
    float* Ks = Qs + UU * QS_PITCH;          // [128][66]
    float* Vs = Ks + CH * KS_PITCH;          // [128][66]
    float* S  = Vs + CH * KS_PITCH;          // [40][130]
    int* sidx = (int*)(S + UU * S_PITCH);    // [40]

    if (t < UU) sidx[t] = g_Mtop[bh * UU + t];
    __syncthreads();

    for (int i = t; i < UU * (DD / 4); i += 256) {
        int j = i >> 4, q4 = i & 15;
        float4 v = *(const float4*)(Q + (((size_t)(b * LL + sidx[j])) * HH + h) * DD + q4 * 4);
        float* dst = Qs + j * QS_PITCH + q4 * 4;
        dst[0] = v.x; dst[1] = v.y; dst[2] = v.z; dst[3] = v.w;
    }
    int k0 = ch * CH;
    for (int i = t; i < CH * (DD / 4); i += 256) {
        int r = i >> 4, q4 = i & 15;
        size_t base = (((size_t)(b * LL + k0 + r)) * HH + h) * DD + q4 * 4;
        float4 kv = *(const float4*)(K + base);
        float4 vv = *(const float4*)(V + base);
        float* dk = Ks + r * KS_PITCH + q4 * 4;
        float* dv = Vs + r * KS_PITCH + q4 * 4;
        dk[0] = kv.x; dk[1] = kv.y; dk[2] = kv.z; dk[3] = kv.w;
        dv[0] = vv.x; dv[1] = vv.y; dv[2] = vv.z; dv[3] = vv.w;
    }
    __syncthreads();

    // ---- phase 1: S[j][k] = scale * dot(Qs[j], Ks[k]) ----
    {
        int kg = t & 31, jg = t >> 5;
        float acc[5][4];
#pragma unroll
        for (int jt = 0; jt < 5; jt++)
#pragma unroll
            for (int kt = 0; kt < 4; kt++) acc[jt][kt] = 0.f;
#pragma unroll 8
        for (int d = 0; d < DD; d++) {
            float qv[5], kv[4];
#pragma unroll
            for (int jt = 0; jt < 5; jt++) qv[jt] = Qs[(jg + 8 * jt) * QS_PITCH + d];
#pragma unroll
            for (int kt = 0; kt < 4; kt++) kv[kt] = Ks[(kg + 32 * kt) * KS_PITCH + d];
#pragma unroll
            for (int jt = 0; jt < 5; jt++)
#pragma unroll
                for (int kt = 0; kt < 4; kt++) acc[jt][kt] += qv[jt] * kv[kt];
        }
#pragma unroll
        for (int jt = 0; jt < 5; jt++)
#pragma unroll
            for (int kt = 0; kt < 4; kt++)
                S[(jg + 8 * jt) * S_PITCH + (kg + 32 * kt)] = acc[jt][kt] * SCALE;
    }
    __syncthreads();

    // ---- phase 2: per-row chunk softmax stats; S <- exp(S - m) ----
    {
        int lane = t & 31, w = t >> 5;
#pragma unroll
        for (int i = 0; i < 5; i++) {
            int j = w * 5 + i;
            float* row = S + j * S_PITCH;
            float v0 = row[lane], v1 = row[lane + 32], v2 = row[lane + 64], v3 = row[lane + 96];
            float m = fmaxf(fmaxf(v0, v1), fmaxf(v2, v3));
            for (int off = 16; off; off >>= 1) m = fmaxf(m, __shfl_xor_sync(0xffffffffu, m, off));
            float e0 = __expf(v0 - m), e1 = __expf(v1 - m);
            float e2 = __expf(v2 - m), e3 = __expf(v3 - m);
            row[lane] = e0; row[lane + 32] = e1; row[lane + 64] = e2; row[lane + 96] = e3;
            float s = e0 + e1 + e2 + e3;
            for (int off = 16; off; off >>= 1) s += __shfl_xor_sync(0xffffffffu, s, off);
            if (lane == 0) {
                g_pm[(bh * UU + j) * NCH + ch] = m;
                g_ps[(bh * UU + j) * NCH + ch] = s;
            }
        }
    }
    __syncthreads();

    // ---- phase 3: partial a[j][d] = sum_k exp * Vs[k][d] (float2 over k) ----
    {
        int d = t & 63, grp = t >> 6;
        float a[10];
#pragma unroll
        for (int jt = 0; jt < 10; jt++) a[jt] = 0.f;
#pragma unroll 2
        for (int k = 0; k < CH; k += 2) {
            float v0 = Vs[k * KS_PITCH + d];
            float v1 = Vs[(k + 1) * KS_PITCH + d];
#pragma unroll
            for (int jt = 0; jt < 10; jt++) {
                float2 sj = *(const float2*)(S + (grp * 10 + jt) * S_PITCH + k);
                a[jt] += sj.x * v0 + sj.y * v1;
            }
        }
#pragma unroll
        for (int jt = 0; jt < 10; jt++)
            g_pa[((bh * UU + grp * 10 + jt) * NCH + ch) * DD + d] = a[jt];
    }
}

// ---------------------------------------------------------------------------
// K6b: merge the 16 chunk partials per (b,h,u); write selected row (over fill).
// ---------------------------------------------------------------------------
__global__ void k_attn_merge(float* __restrict__ out) {
    int u  = blockIdx.x % UU;
    int bh = blockIdx.x / UU;
    int b = bh >> 3, h = bh & 7;
    int d = threadIdx.x;
    int base = (bh * UU + u) * NCH;
    float gm = -CUDART_INF_F;
#pragma unroll
    for (int c = 0; c < NCH; c++) gm = fmaxf(gm, g_pm[base + c]);
    float tot = 0.f, val = 0.f;
#pragma unroll
    for (int c = 0; c < NCH; c++) {
        float e = __expf(g_pm[base + c] - gm);
        tot += g_ps[base + c] * e;
        val += g_pa[(base + c) * DD + d] * e;
    }
    int lq = g_Mtop[bh * UU + u];
    out[(((size_t)(b * LL + lq)) * HH + h) * DD + d] = val / tot;
}

// ---------------------------------------------------------------------------
// Launch: two-branch DAG.
//   branch A (stream 0): prep -> sampleM4 -> topk -> attn_part
//   branch B (side)    : zero -> vmean -> fill
//   join               : attn_merge (needs attn_part + fill)
// Streams/events are created once on the first (uncaptured) call; the fork/
// join event pattern is graph-capture legal and allocation-free.
// ---------------------------------------------------------------------------
extern "C" void kernel_launch(void* const* d_in, const int* in_sizes, int n_in,
                              void* d_out, int out_size) {
    const float* Q = (const float*)d_in[0];
    const float* K = (const float*)d_in[1];
    const float* V = (const float*)d_in[2];
    float* out = (float*)d_out;

    static cudaStream_t s2 = nullptr;
    static cudaEvent_t evFork = nullptr, evJoin = nullptr;
    if (s2 == nullptr) {
        cudaStreamCreateWithFlags(&s2, cudaStreamNonBlocking);
        cudaEventCreateWithFlags(&evFork, cudaEventDisableTiming);
        cudaEventCreateWithFlags(&evJoin, cudaEventDisableTiming);
        cudaFuncSetAttribute(k_attn_part, cudaFuncAttributeMaxDynamicSharedMemorySize,
                             SH_BYTES);
        cudaFuncSetAttribute(k_sampleM4, cudaFuncAttributeMaxDynamicSharedMemorySize,
                             SMP_SH_BYTES);
    }

    // fork side branch (depends only on V / device globals)
    cudaEventRecord(evFork, 0);
    cudaStreamWaitEvent(s2, evFork, 0);
    k_zero<<<(BH * DD) / 1024, 1024, 0, s2>>>();
    k_vmean<<<BH * 32, 256, 0, s2>>>(V);
    k_fill<<<(BB * LL * HH * (DD / 4)) / 256, 256, 0, s2>>>(out);
    cudaEventRecord(evJoin, s2);

    // critical path
    k_prep<<<LL / 64, 64>>>();
    k_sampleM4<<<BH * NCHB, 1024, SMP_SH_BYTES>>>(Q, K);
    k_topk<<<BH, 1024>>>();
    k_attn_part<<<BH * NCH, 256, SH_BYTES>>>(Q, K, V);

    // join: attn_merge needs fill's output in place
    cudaStreamWaitEvent(0, evJoin, 0);
    k_attn_merge<<<BH * UU, DD>>>(out);
}

// round 15
// speedup vs baseline: 1.0458x; 1.0458x over previous
#include <cuda_runtime.h>
#include <stdint.h>
#include <math_constants.h>

// ProbSparse attention (Informer) — B=4, L=2048, H=8, D=64, U_part=u=40.
// Layout of all tensors: (B, L, H, D) row-major.

#define BB 4
#define LL 2048
#define HH 8
#define DD 64
#define UU 40
#define SS 40
#define BH (BB*HH)       // 32
#define NCHB 4           // key chunks for sampled-score bucketing
#define CKEY 512         // keys per bucket chunk
#define CSH  9           // log2(CKEY)
#define NCH 16           // key chunks for split-K attention
#define CH  128
#define SCALE 0.125f

__device__ __align__(16) uint16_t g_cnt16[NCHB*LL];
__device__ __align__(16) uint16_t g_pairs2[NCHB*LL*SS];   // [c][l][<=40]
__device__ __align__(16) float    g_pM[NCHB*BH*LL];
__device__ __align__(16) float    g_pS[NCHB*BH*LL];
__device__ __align__(16) int      g_Mtop[BH*UU];
__device__ __align__(16) float    g_Vmean[BH*DD];
__device__ __align__(16) float    g_pm[BH*UU*NCH];
__device__ __align__(16) float    g_ps[BH*UU*NCH];
__device__ __align__(16) float    g_pa[BH*UU*NCH*DD];

// ---------------------------------------------------------------------------
// Threefry-2x32-20, constexpr-evaluable.
// ---------------------------------------------------------------------------
__host__ __device__ constexpr uint64_t tf2x32(uint32_t k0, uint32_t k1,
                                              uint32_t c0, uint32_t c1) {
    uint32_t ks0 = k0, ks1 = k1, ks2 = k0 ^ k1 ^ 0x1BD11BDAu;
    uint32_t x0 = c0 + ks0, x1 = c1 + ks1;
    const int rotA[4] = {13, 15, 26, 6};
    const int rotB[4] = {17, 29, 16, 24};
    for (int g = 0; g < 5; g++) {
        const int* rot = (g & 1) ? rotB : rotA;
        for (int r = 0; r < 4; r++) {
            x0 += x1;
            x1 = (x1 << rot[r]) | (x1 >> (32 - rot[r]));
            x1 ^= x0;
        }
        uint32_t inj0 = 0, inj1 = 0;
        switch (g) {
            case 0: inj0 = ks1; inj1 = ks2 + 1u; break;
            case 1: inj0 = ks2; inj1 = ks0 + 2u; break;
            case 2: inj0 = ks0; inj1 = ks1 + 3u; break;
            case 3: inj0 = ks1; inj1 = ks2 + 4u; break;
            case 4: inj0 = ks2; inj1 = ks0 + 5u; break;
        }
        x0 += inj0; x1 += inj1;
    }
    return ((uint64_t)x0 << 32) | (uint64_t)x1;
}

constexpr uint64_t K2PAIR = tf2x32(0u, 42u, 0u, 1u);
#define K2_HI ((uint32_t)(K2PAIR >> 32))
#define K2_LO ((uint32_t)(K2PAIR & 0xffffffffu))

// ---------------------------------------------------------------------------
// K0 (side stream): zero g_Vmean.
// ---------------------------------------------------------------------------
__global__ void k_zero() {
    int i = blockIdx.x * 1024 + threadIdx.x;
    g_Vmean[i] = 0.f;
}

// ---------------------------------------------------------------------------
// K1: warp-parallel rng+count+rank. One WARP per query row l.
// Lane i computes the hash for sample s=i; lanes 0..7 also s=32+i.
// Stable ranks within each (chunk,l) bucket via ballot+popc — identical
// ordering to the sequential s-order scatter.
// ---------------------------------------------------------------------------
__device__ __forceinline__ uint32_t tf_fold(uint32_t c1v) {
    uint64_t y = tf2x32(K2_HI, K2_LO, 0u, c1v);
    return (uint32_t)(y >> 32) ^ (uint32_t)(y & 0xffffffffu);
}

__global__ void k_prep() {
    int lane = threadIdx.x & 31;
    int l = blockIdx.x * 8 + (threadIdx.x >> 5);   // 8 warps/block, 256 blocks

    // hash sample s = lane (all lanes) and s = 32+lane (lanes 0..7)
    int idx1 = (int)(tf_fold((uint32_t)(l * SS + lane)) & (LL - 1));
    int idx2 = 0;
    if (lane < 8)
        idx2 = (int)(tf_fold((uint32_t)(l * SS + 32 + lane)) & (LL - 1));

    int c1 = idx1 >> CSH;
    int c2 = (lane < 8) ? (idx2 >> CSH) : -1;

    // per-chunk ballots over batch 1 (s=0..31) and batch 2 (s=32..39)
    uint32_t m1[NCHB], m2[NCHB];
#pragma unroll
    for (int c = 0; c < NCHB; c++) {
        m1[c] = __ballot_sync(0xffffffffu, c1 == c);
        m2[c] = __ballot_sync(0xffffffffu, c2 == c);
    }
    uint32_t ltmask = (1u << lane) - 1u;

    // first-batch scatter: rank = earlier same-chunk lanes in batch 1
    uint32_t mm1 = (c1 == 0) ? m1[0] : (c1 == 1) ? m1[1] : (c1 == 2) ? m1[2] : m1[3];
    int r1 = __popc(mm1 & ltmask);
    g_pairs2[(c1 * LL + l) * SS + r1] = (uint16_t)(idx1 & (CKEY - 1));

    // second-batch scatter: rank = all batch-1 same-chunk + earlier batch-2
    if (lane < 8) {
        uint32_t mm1b = (c2 == 0) ? m1[0] : (c2 == 1) ? m1[1] : (c2 == 2) ? m1[2] : m1[3];
        uint32_t mm2  = (c2 == 0) ? m2[0] : (c2 == 1) ? m2[1] : (c2 == 2) ? m2[2] : m2[3];
        int r2 = __popc(mm1b) + __popc(mm2 & ltmask);
        g_pairs2[(c2 * LL + l) * SS + r2] = (uint16_t)(idx2 & (CKEY - 1));
    }

    // counts
    if (lane < NCHB)
        g_cnt16[lane * LL + l] = (uint16_t)(__popc(m1[lane]) + __popc(m2[lane]));
}

// ---------------------------------------------------------------------------
// K2: sampled-score partials (PROVEN R10 variant). Block = (bh, chunk of 512
// keys) -> 128 blocks, 1024 threads (32 warps), 132KB smem. Conflict-free
// octet LDS scheme.
// ---------------------------------------------------------------------------
#define SMP_SH_BYTES (CKEY*DD*4 + LL*2)

__global__ void __launch_bounds__(1024, 1) k_sampleM4(const float* __restrict__ Q,
                                                      const float* __restrict__ K) {
    int c  = blockIdx.x & (NCHB - 1);
    int bh = blockIdx.x >> 2;
    int b = bh >> 3, h = bh & 7;

    extern __shared__ float sk[];                    // [512][64]
    uint16_t* scnt = (uint16_t*)(sk + CKEY * DD);    // [2048]

    const float* Kc = K + ((size_t)(b * LL + c * CKEY) * HH + h) * DD;
    for (int i = threadIdx.x; i < CKEY * (DD / 4); i += 1024) {
        int r = i >> 4, q4 = i & 15;
        float4 v = __ldcg((const float4*)(Kc + (size_t)r * (HH * DD) + q4 * 4));
        *(float4*)(sk + r * DD + q4 * 4) = v;
    }
    for (int i = threadIdx.x; i < LL; i += 1024)
        scnt[i] = g_cnt16[c * LL + i];
    __syncthreads();

    int lane = threadIdx.x & 31, wid = threadIdx.x >> 5;
    int oct = lane >> 3;           // sample slot 0..3
    int oj  = lane & 7;            // position within octet

    for (int l = wid; l < LL; l += 32) {
        int cnt = (int)scnt[l];
        const float* qrow = Q + ((size_t)(b * LL + l) * HH + h) * DD;
        float4 qa = __ldcg((const float4*)(qrow + oj * 4));
        float4 qb = __ldcg((const float4*)(qrow + 32 + oj * 4));
        const uint16_t* pr = g_pairs2 + (c * LL + l) * SS;
        int pa = (lane < cnt) ? (int)pr[lane] : 0;
        int pb = (lane + 32 < cnt) ? (int)pr[lane + 32] : 0;

        float mx = -CUDART_INF_F, sm = 0.f;
        for (int t0 = 0; t0 < cnt; t0 += 4) {
            int src = t0 + oct;
            int kloc = (t0 < 32)
                     ? __shfl_sync(0xffffffffu, pa, src & 31)
                     : __shfl_sync(0xffffffffu, pb, src - 32);
            bool valid = src < cnt;
            const float* krow = sk + kloc * DD;
            float4 ka = *(const float4*)(krow + oj * 4);
            float4 kb = *(const float4*)(krow + 32 + oj * 4);
            float p = qa.x * ka.x + qa.y * ka.y + qa.z * ka.z + qa.w * ka.w
                    + qb.x * kb.x + qb.y * kb.y + qb.z * kb.z + qb.w * kb.w;
            p += __shfl_xor_sync(0xffffffffu, p, 1);
            p += __shfl_xor_sync(0xffffffffu, p, 2);
            p += __shfl_xor_sync(0xffffffffu, p, 4);
            if (valid) { mx = fmaxf(mx, p); sm += p; }
        }
        mx = fmaxf(mx, __shfl_xor_sync(0xffffffffu, mx, 8));
        mx = fmaxf(mx, __shfl_xor_sync(0xffffffffu, mx, 16));
        sm += __shfl_xor_sync(0xffffffffu, sm, 8);
        sm += __shfl_xor_sync(0xffffffffu, sm, 16);
        if (lane == 0) {
            g_pM[(c * BH + bh) * LL + l] = mx;
            g_pS[(c * BH + bh) * LL + l] = sm;
        }
    }
}

// ---------------------------------------------------------------------------
// K3: merge 4 chunk partials -> M, then exact top-40 per (b,h) via bitonic
// sort of (value,index), comparator (v desc, idx asc). 1024 threads.
// ---------------------------------------------------------------------------
__global__ void k_topk() {
    int bh = blockIdx.x;
    __shared__ float sv[LL];
    __shared__ int   si[LL];
    int t = threadIdx.x;
    for (int i = t; i < LL; i += 1024) {
        float mm = -CUDART_INF_F, s = 0.f;
#pragma unroll
        for (int c = 0; c < NCHB; c++) {
            mm = fmaxf(mm, g_pM[(c * BH + bh) * LL + i]);
            s += g_pS[(c * BH + bh) * LL + i];
        }
        sv[i] = mm - s * (1.0f / (float)LL);
        si[i] = i;
    }
    __syncthreads();
    for (int k = 2; k <= LL; k <<= 1) {
        for (int j = k >> 1; j > 0; j >>= 1) {
            for (int i = t; i < LL; i += 1024) {
                int p = i ^ j;
                if (p > i) {
                    bool asc = (i & k) == 0;
                    float va = sv[i], vp = sv[p];
                    int   ia = si[i], ip = si[p];
                    bool pre = (vp > va) || (vp == va && ip < ia);
                    if (asc == pre) {
                        sv[i] = vp; sv[p] = va;
                        si[i] = ip; si[p] = ia;
                    }
                }
            }
            __syncthreads();
        }
    }
    if (t < UU) g_Mtop[bh * UU + t] = si[t];
}

// ---------------------------------------------------------------------------
// K4: V_mean partials; 1024 blocks (bh x 32 L-chunks of 64), atomicAdd merge.
// ---------------------------------------------------------------------------
__global__ void k_vmean(const float* __restrict__ V) {
    int blk = blockIdx.x;
    int bh = blk >> 5, chn = blk & 31;
    int b = bh >> 3, h = bh & 7;
    int t = threadIdx.x;
    int d = t & 63, sub = t >> 6;
    float s = 0.f;
#pragma unroll 16
    for (int i = 0; i < 16; i++) {
        int l = chn * 64 + sub + i * 4;
        s += V[(((size_t)(b * LL + l)) * HH + h) * DD + d];
    }
    __shared__ float red[256];
    red[t] = s;
    __syncthreads();
    if (t < 64) {
        float tot = red[t] + red[t + 64] + red[t + 128] + red[t + 192];
        atomicAdd(&g_Vmean[bh * DD + t], tot * (1.0f / (float)LL));
    }
}

// ---------------------------------------------------------------------------
// K5: out[b,l,h,:] = V_mean[b,h,:] for all l.
// ---------------------------------------------------------------------------
__global__ void k_fill(float* __restrict__ out) {
    int i = blockIdx.x * blockDim.x + threadIdx.x;
    if (i >= BB * LL * HH * (DD / 4)) return;
    int q4  = i & 15;
    int row = i >> 4;
    int h = row & 7;
    int b = row >> 14;
    float4 vm = reinterpret_cast<const float4*>(g_Vmean)[((b << 3) + h) * (DD / 4) + q4];
    reinterpret_cast<float4*>(out)[i] = vm;
}

// ---------------------------------------------------------------------------
// K6a: split-K attention partials. Block = (b,h, key-chunk of 128), 256 thr.
// ---------------------------------------------------------------------------
#define QS_PITCH 66
#define KS_PITCH 66
#define S_PITCH  130
#define SH_FLOATS (UU*QS_PITCH + CH*KS_PITCH + CH*KS_PITCH + UU*S_PITCH)
#define SH_BYTES  (SH_FLOATS*4 + UU*4)

__global__ void k_attn_part(const float* __restrict__ Q, const float* __restrict__ K,
                            const float* __restrict__ V) {
    int ch = blockIdx.x & (NCH - 1);
    int bh = blockIdx.x >> 4;
    int b = bh >> 3, h = bh & 7;
    int t = threadIdx.x;

    extern __shared__ float sh[];
    float* Qs = sh;                          // [40][66]
    float* Ks = Qs + UU * QS_PITCH;          // [128][66]
    float* Vs = Ks + CH * KS_PITCH;          // [128][66]
    float* S  = Vs + CH * KS_PITCH;          // [40][130]
    int* sidx = (int*)(S + UU * S_PITCH);    // [40]

    if (t < UU) sidx[t] = g_Mtop[bh * UU + t];
    __syncthreads();

    for (int i = t; i < UU * (DD / 4); i += 256) {
        int j = i >> 4, q4 = i & 15;
        float4 v = *(const float4*)(Q + (((size_t)(b * LL + sidx[j])) * HH + h) * DD + q4 * 4);
        float* dst = Qs + j * QS_PITCH + q4 * 4;
        dst[0] = v.x; dst[1] = v.y; dst[2] = v.z; dst[3] = v.w;
    }
    int k0 = ch * CH;
    for (int i = t; i < CH * (DD / 4); i += 256) {
        int r = i >> 4, q4 = i & 15;
        size_t base = (((size_t)(b * LL + k0 + r)) * HH + h) * DD + q4 * 4;
        float4 kv = *(const float4*)(K + base);
        float4 vv = *(const float4*)(V + base);
        float* dk = Ks + r * KS_PITCH + q4 * 4;
        float* dv = Vs + r * KS_PITCH + q4 * 4;
        dk[0] = kv.x; dk[1] = kv.y; dk[2] = kv.z; dk[3] = kv.w;
        dv[0] = vv.x; dv[1] = vv.y; dv[2] = vv.z; dv[3] = vv.w;
    }
    __syncthreads();

    // ---- phase 1: S[j][k] = scale * dot(Qs[j], Ks[k]) ----
    {
        int kg = t & 31, jg = t >> 5;
        float acc[5][4];
#pragma unroll
        for (int jt = 0; jt < 5; jt++)
#pragma unroll
            for (int kt = 0; kt < 4; kt++) acc[jt][kt] = 0.f;
#pragma unroll 8
        for (int d = 0; d < DD; d++) {
            float qv[5], kv[4];
#pragma unroll
            for (int jt = 0; jt < 5; jt++) qv[jt] = Qs[(jg + 8 * jt) * QS_PITCH + d];
#pragma unroll
            for (int kt = 0; kt < 4; kt++) kv[kt] = Ks[(kg + 32 * kt) * KS_PITCH + d];
#pragma unroll
            for (int jt = 0; jt < 5; jt++)
#pragma unroll
                for (int kt = 0; kt < 4; kt++) acc[jt][kt] += qv[jt] * kv[kt];
        }
#pragma unroll
        for (int jt = 0; jt < 5; jt++)
#pragma unroll
            for (int kt = 0; kt < 4; kt++)
                S[(jg + 8 * jt) * S_PITCH + (kg + 32 * kt)] = acc[jt][kt] * SCALE;
    }
    __syncthreads();

    // ---- phase 2: per-row chunk softmax stats; S <- exp(S - m) ----
    {
        int lane = t & 31, w = t >> 5;
#pragma unroll
        for (int i = 0; i < 5; i++) {
            int j = w * 5 + i;
            float* row = S + j * S_PITCH;
            float v0 = row[lane], v1 = row[lane + 32], v2 = row[lane + 64], v3 = row[lane + 96];
            float m = fmaxf(fmaxf(v0, v1), fmaxf(v2, v3));
            for (int off = 16; off; off >>= 1) m = fmaxf(m, __shfl_xor_sync(0xffffffffu, m, off));
            float e0 = __expf(v0 - m), e1 = __expf(v1 - m);
            float e2 = __expf(v2 - m), e3 = __expf(v3 - m);
            row[lane] = e0; row[lane + 32] = e1; row[lane + 64] = e2; row[lane + 96] = e3;
            float s = e0 + e1 + e2 + e3;
            for (int off = 16; off; off >>= 1) s += __shfl_xor_sync(0xffffffffu, s, off);
            if (lane == 0) {
                g_pm[(bh * UU + j) * NCH + ch] = m;
                g_ps[(bh * UU + j) * NCH + ch] = s;
            }
        }
    }
    __syncthreads();

    // ---- phase 3: partial a[j][d] = sum_k exp * Vs[k][d] (float2 over k) ----
    {
        int d = t & 63, grp = t >> 6;
        float a[10];
#pragma unroll
        for (int jt = 0; jt < 10; jt++) a[jt] = 0.f;
#pragma unroll 2
        for (int k = 0; k < CH; k += 2) {
            float v0 = Vs[k * KS_PITCH + d];
            float v1 = Vs[(k + 1) * KS_PITCH + d];
#pragma unroll
            for (int jt = 0; jt < 10; jt++) {
                float2 sj = *(const float2*)(S + (grp * 10 + jt) * S_PITCH + k);
                a[jt] += sj.x * v0 + sj.y * v1;
            }
        }
#pragma unroll
        for (int jt = 0; jt < 10; jt++)
            g_pa[((bh * UU + grp * 10 + jt) * NCH + ch) * DD + d] = a[jt];
    }
}

// ---------------------------------------------------------------------------
// K6b: merge the 16 chunk partials per (b,h,u); write selected row (over fill).
// ---------------------------------------------------------------------------
__global__ void k_attn_merge(float* __restrict__ out) {
    int u  = blockIdx.x % UU;
    int bh = blockIdx.x / UU;
    int b = bh >> 3, h = bh & 7;
    int d = threadIdx.x;
    int base = (bh * UU + u) * NCH;
    float gm = -CUDART_INF_F;
#pragma unroll
    for (int c = 0; c < NCH; c++) gm = fmaxf(gm, g_pm[base + c]);
    float tot = 0.f, val = 0.f;
#pragma unroll
    for (int c = 0; c < NCH; c++) {
        float e = __expf(g_pm[base + c] - gm);
        tot += g_ps[base + c] * e;
        val += g_pa[(base + c) * DD + d] * e;
    }
    int lq = g_Mtop[bh * UU + u];
    out[(((size_t)(b * LL + lq)) * HH + h) * DD + d] = val / tot;
}

// ---------------------------------------------------------------------------
// Launch: two-branch DAG (fork/join via events; capture-legal, alloc-free).
// ---------------------------------------------------------------------------
extern "C" void kernel_launch(void* const* d_in, const int* in_sizes, int n_in,
                              void* d_out, int out_size) {
    const float* Q = (const float*)d_in[0];
    const float* K = (const float*)d_in[1];
    const float* V = (const float*)d_in[2];
    float* out = (float*)d_out;

    static cudaStream_t s2 = nullptr;
    static cudaEvent_t evFork = nullptr, evJoin = nullptr;
    if (s2 == nullptr) {
        cudaStreamCreateWithFlags(&s2, cudaStreamNonBlocking);
        cudaEventCreateWithFlags(&evFork, cudaEventDisableTiming);
        cudaEventCreateWithFlags(&evJoin, cudaEventDisableTiming);
        cudaFuncSetAttribute(k_attn_part, cudaFuncAttributeMaxDynamicSharedMemorySize,
                             SH_BYTES);
        cudaFuncSetAttribute(k_sampleM4, cudaFuncAttributeMaxDynamicSharedMemorySize,
                             SMP_SH_BYTES);
    }

    // fork side branch (depends only on V / device globals)
    cudaEventRecord(evFork, 0);
    cudaStreamWaitEvent(s2, evFork, 0);
    k_zero<<<(BH * DD) / 1024, 1024, 0, s2>>>();
    k_vmean<<<BH * 32, 256, 0, s2>>>(V);
    k_fill<<<(BB * LL * HH * (DD / 4)) / 256, 256, 0, s2>>>(out);
    cudaEventRecord(evJoin, s2);

    // critical path
    k_prep<<<LL / 8, 256>>>();
    k_sampleM4<<<BH * NCHB, 1024, SMP_SH_BYTES>>>(Q, K);
    k_topk<<<BH, 1024>>>();
    k_attn_part<<<BH * NCH, 256, SH_BYTES>>>(Q, K, V);

    // join: attn_merge needs fill's output in place
    cudaStreamWaitEvent(0, evJoin, 0);
    k_attn_merge<<<BH * UU, DD>>>(out);
}

// round 16
// speedup vs baseline: 1.0541x; 1.0079x over previous
#include <cuda_runtime.h>
#include <stdint.h>
#include <math_constants.h>

// ProbSparse attention (Informer) — B=4, L=2048, H=8, D=64, U_part=u=40.
// Layout of all tensors: (B, L, H, D) row-major.

#define BB 4
#define LL 2048
#define HH 8
#define DD 64
#define UU 40
#define SS 40
#define BH (BB*HH)       // 32
#define NCHB 4           // key chunks for sampled-score bucketing
#define CKEY 512         // keys per bucket chunk
#define CSH  9           // log2(CKEY)
#define NCH 16           // key chunks for split-K attention
#define CH  128
#define SCALE 0.125f

__device__ __align__(16) uint16_t g_cnt16[NCHB*LL];
__device__ __align__(16) uint16_t g_pairs2[NCHB*LL*SS];   // [c][l][<=40]
__device__ __align__(16) float    g_pM[NCHB*BH*LL];
__device__ __align__(16) float    g_pS[NCHB*BH*LL];
__device__ __align__(16) int      g_Mtop[BH*UU];
__device__ __align__(16) float    g_Vmean[BH*DD];
__device__ __align__(16) float    g_pm[BH*UU*NCH];
__device__ __align__(16) float    g_ps[BH*UU*NCH];
__device__ __align__(16) float    g_pa[BH*UU*NCH*DD];

// ---------------------------------------------------------------------------
// Threefry-2x32-20, constexpr-evaluable.
// ---------------------------------------------------------------------------
__host__ __device__ constexpr uint64_t tf2x32(uint32_t k0, uint32_t k1,
                                              uint32_t c0, uint32_t c1) {
    uint32_t ks0 = k0, ks1 = k1, ks2 = k0 ^ k1 ^ 0x1BD11BDAu;
    uint32_t x0 = c0 + ks0, x1 = c1 + ks1;
    const int rotA[4] = {13, 15, 26, 6};
    const int rotB[4] = {17, 29, 16, 24};
    for (int g = 0; g < 5; g++) {
        const int* rot = (g & 1) ? rotB : rotA;
        for (int r = 0; r < 4; r++) {
            x0 += x1;
            x1 = (x1 << rot[r]) | (x1 >> (32 - rot[r]));
            x1 ^= x0;
        }
        uint32_t inj0 = 0, inj1 = 0;
        switch (g) {
            case 0: inj0 = ks1; inj1 = ks2 + 1u; break;
            case 1: inj0 = ks2; inj1 = ks0 + 2u; break;
            case 2: inj0 = ks0; inj1 = ks1 + 3u; break;
            case 3: inj0 = ks1; inj1 = ks2 + 4u; break;
            case 4: inj0 = ks2; inj1 = ks0 + 5u; break;
        }
        x0 += inj0; x1 += inj1;
    }
    return ((uint64_t)x0 << 32) | (uint64_t)x1;
}

constexpr uint64_t K2PAIR = tf2x32(0u, 42u, 0u, 1u);
#define K2_HI ((uint32_t)(K2PAIR >> 32))
#define K2_LO ((uint32_t)(K2PAIR & 0xffffffffu))

// ---------------------------------------------------------------------------
// K0 (side stream): zero g_Vmean.
// ---------------------------------------------------------------------------
__global__ void k_zero() {
    int i = blockIdx.x * 1024 + threadIdx.x;
    g_Vmean[i] = 0.f;
}

// ---------------------------------------------------------------------------
// K1: warp-parallel rng+count+rank (ballot/popc stable scatter).
// ---------------------------------------------------------------------------
__device__ __forceinline__ uint32_t tf_fold(uint32_t c1v) {
    uint64_t y = tf2x32(K2_HI, K2_LO, 0u, c1v);
    return (uint32_t)(y >> 32) ^ (uint32_t)(y & 0xffffffffu);
}

__global__ void k_prep() {
    int lane = threadIdx.x & 31;
    int l = blockIdx.x * 8 + (threadIdx.x >> 5);   // 8 warps/block, 256 blocks

    int idx1 = (int)(tf_fold((uint32_t)(l * SS + lane)) & (LL - 1));
    int idx2 = 0;
    if (lane < 8)
        idx2 = (int)(tf_fold((uint32_t)(l * SS + 32 + lane)) & (LL - 1));

    int c1 = idx1 >> CSH;
    int c2 = (lane < 8) ? (idx2 >> CSH) : -1;

    uint32_t m1[NCHB], m2[NCHB];
#pragma unroll
    for (int c = 0; c < NCHB; c++) {
        m1[c] = __ballot_sync(0xffffffffu, c1 == c);
        m2[c] = __ballot_sync(0xffffffffu, c2 == c);
    }
    uint32_t ltmask = (1u << lane) - 1u;

    uint32_t mm1 = (c1 == 0) ? m1[0] : (c1 == 1) ? m1[1] : (c1 == 2) ? m1[2] : m1[3];
    int r1 = __popc(mm1 & ltmask);
    g_pairs2[(c1 * LL + l) * SS + r1] = (uint16_t)(idx1 & (CKEY - 1));

    if (lane < 8) {
        uint32_t mm1b = (c2 == 0) ? m1[0] : (c2 == 1) ? m1[1] : (c2 == 2) ? m1[2] : m1[3];
        uint32_t mm2  = (c2 == 0) ? m2[0] : (c2 == 1) ? m2[1] : (c2 == 2) ? m2[2] : m2[3];
        int r2 = __popc(mm1b) + __popc(mm2 & ltmask);
        g_pairs2[(c2 * LL + l) * SS + r2] = (uint16_t)(idx2 & (CKEY - 1));
    }

    if (lane < NCHB)
        g_cnt16[lane * LL + l] = (uint16_t)(__popc(m1[lane]) + __popc(m2[lane]));
}

// ---------------------------------------------------------------------------
// K2: sampled-score partials — DUAL-QUERY warps. Block = (bh, chunk of 512
// keys), 1024 threads, 132KB smem. Each warp processes two query rows
// (lA = l, lB = l+1024) as two independent register chains per iteration,
// doubling latency coverage. Conflict-free octet LDS scheme (pitch 64;
// each quarter-warp phase reads one contiguous 128B row segment).
// Slot-accumulator fold order per l identical to the single-l version.
// ---------------------------------------------------------------------------
#define SMP_SH_BYTES (CKEY*DD*4 + LL*2)

__global__ void __launch_bounds__(1024, 1) k_sampleM7(const float* __restrict__ Q,
                                                      const float* __restrict__ K) {
    int c  = blockIdx.x & (NCHB - 1);
    int bh = blockIdx.x >> 2;
    int b = bh >> 3, h = bh & 7;

    extern __shared__ float sk[];                    // [512][64]
    uint16_t* scnt = (uint16_t*)(sk + CKEY * DD);    // [2048]

    const float* Kc = K + ((size_t)(b * LL + c * CKEY) * HH + h) * DD;
    for (int i = threadIdx.x; i < CKEY * (DD / 4); i += 1024) {
        int r = i >> 4, q4 = i & 15;
        float4 v = __ldcg((const float4*)(Kc + (size_t)r * (HH * DD) + q4 * 4));
        *(float4*)(sk + r * DD + q4 * 4) = v;
    }
    for (int i = threadIdx.x; i < LL; i += 1024)
        scnt[i] = g_cnt16[c * LL + i];
    __syncthreads();

    int lane = threadIdx.x & 31, wid = threadIdx.x >> 5;
    int oct = lane >> 3;           // sample slot 0..3
    int oj4 = (lane & 7) * 4;      // float offset within 128B segment

    for (int l = wid; l < LL / 2; l += 32) {
        int lA = l, lB = l + LL / 2;
        int cntA = (int)scnt[lA];
        int cntB = (int)scnt[lB];

        const float* qrA = Q + ((size_t)(b * LL + lA) * HH + h) * DD;
        const float* qrB = Q + ((size_t)(b * LL + lB) * HH + h) * DD;
        float4 qaA = __ldcg((const float4*)(qrA + oj4));
        float4 qbA = __ldcg((const float4*)(qrA + 32 + oj4));
        float4 qaB = __ldcg((const float4*)(qrB + oj4));
        float4 qbB = __ldcg((const float4*)(qrB + 32 + oj4));

        const uint16_t* prA = g_pairs2 + (c * LL + lA) * SS;
        const uint16_t* prB = g_pairs2 + (c * LL + lB) * SS;
        int paA = (lane < cntA) ? (int)prA[lane] : 0;
        int paB = (lane < cntB) ? (int)prB[lane] : 0;

        float mxA = -CUDART_INF_F, smA = 0.f;
        float mxB = -CUDART_INF_F, smB = 0.f;

        int mc = max(cntA, cntB);
        int lim = min(mc, 32);
        for (int t0 = 0; t0 < lim; t0 += 4) {
            int srcl = (t0 + oct) & 31;
            int kA = __shfl_sync(0xffffffffu, paA, srcl);
            int kB = __shfl_sync(0xffffffffu, paB, srcl);
            const float* ra = sk + kA * DD;
            const float* rb = sk + kB * DD;
            float4 kaA = *(const float4*)(ra + oj4);
            float4 kbA = *(const float4*)(ra + 32 + oj4);
            float4 kaB = *(const float4*)(rb + oj4);
            float4 kbB = *(const float4*)(rb + 32 + oj4);
            float pA = qaA.x * kaA.x + qaA.y * kaA.y + qaA.z * kaA.z + qaA.w * kaA.w
                     + qbA.x * kbA.x + qbA.y * kbA.y + qbA.z * kbA.z + qbA.w * kbA.w;
            float pB = qaB.x * kaB.x + qaB.y * kaB.y + qaB.z * kaB.z + qaB.w * kaB.w
                     + qbB.x * kbB.x + qbB.y * kbB.y + qbB.z * kbB.z + qbB.w * kbB.w;
            pA += __shfl_xor_sync(0xffffffffu, pA, 1);
            pB += __shfl_xor_sync(0xffffffffu, pB, 1);
            pA += __shfl_xor_sync(0xffffffffu, pA, 2);
            pB += __shfl_xor_sync(0xffffffffu, pB, 2);
            pA += __shfl_xor_sync(0xffffffffu, pA, 4);
            pB += __shfl_xor_sync(0xffffffffu, pB, 4);
            if (t0 + oct < cntA) { mxA = fmaxf(mxA, pA); smA += pA; }
            if (t0 + oct < cntB) { mxB = fmaxf(mxB, pB); smB += pB; }
        }
        // rare tails (cnt > 32), warp-uniform branches
        if (cntA > 32) {
            int pbA = (lane + 32 < cntA) ? (int)prA[lane + 32] : 0;
            for (int t0 = 32; t0 < cntA; t0 += 4) {
                int kA = __shfl_sync(0xffffffffu, pbA, (t0 - 32) + oct);
                const float* ra = sk + kA * DD;
                float4 kaA = *(const float4*)(ra + oj4);
                float4 kbA = *(const float4*)(ra + 32 + oj4);
                float pA = qaA.x * kaA.x + qaA.y * kaA.y + qaA.z * kaA.z + qaA.w * kaA.w
                         + qbA.x * kbA.x + qbA.y * kbA.y + qbA.z * kbA.z + qbA.w * kbA.w;
                pA += __shfl_xor_sync(0xffffffffu, pA, 1);
                pA += __shfl_xor_sync(0xffffffffu, pA, 2);
                pA += __shfl_xor_sync(0xffffffffu, pA, 4);
                if (t0 + oct < cntA) { mxA = fmaxf(mxA, pA); smA += pA; }
            }
        }
        if (cntB > 32) {
            int pbB = (lane + 32 < cntB) ? (int)prB[lane + 32] : 0;
            for (int t0 = 32; t0 < cntB; t0 += 4) {
                int kB = __shfl_sync(0xffffffffu, pbB, (t0 - 32) + oct);
                const float* rb = sk + kB * DD;
                float4 kaB = *(const float4*)(rb + oj4);
                float4 kbB = *(const float4*)(rb + 32 + oj4);
                float pB = qaB.x * kaB.x + qaB.y * kaB.y + qaB.z * kaB.z + qaB.w * kaB.w
                         + qbB.x * kbB.x + qbB.y * kbB.y + qbB.z * kbB.z + qbB.w * kbB.w;
                pB += __shfl_xor_sync(0xffffffffu, pB, 1);
                pB += __shfl_xor_sync(0xffffffffu, pB, 2);
                pB += __shfl_xor_sync(0xffffffffu, pB, 4);
                if (t0 + oct < cntB) { mxB = fmaxf(mxB, pB); smB += pB; }
            }
        }
        // fold slot accumulators (same order as single-l version)
        mxA = fmaxf(mxA, __shfl_xor_sync(0xffffffffu, mxA, 8));
        mxB = fmaxf(mxB, __shfl_xor_sync(0xffffffffu, mxB, 8));
        mxA = fmaxf(mxA, __shfl_xor_sync(0xffffffffu, mxA, 16));
        mxB = fmaxf(mxB, __shfl_xor_sync(0xffffffffu, mxB, 16));
        smA += __shfl_xor_sync(0xffffffffu, smA, 8);
        smB += __shfl_xor_sync(0xffffffffu, smB, 8);
        smA += __shfl_xor_sync(0xffffffffu, smA, 16);
        smB += __shfl_xor_sync(0xffffffffu, smB, 16);
        if (lane == 0) {
            g_pM[(c * BH + bh) * LL + lA] = mxA;
            g_pS[(c * BH + bh) * LL + lA] = smA;
            g_pM[(c * BH + bh) * LL + lB] = mxB;
            g_pS[(c * BH + bh) * LL + lB] = smB;
        }
    }
}

// ---------------------------------------------------------------------------
// K3: merge 4 chunk partials -> M, then exact top-40 per (b,h) via bitonic
// sort of (value,index), comparator (v desc, idx asc). 1024 threads.
// ---------------------------------------------------------------------------
__global__ void k_topk() {
    int bh = blockIdx.x;
    __shared__ float sv[LL];
    __shared__ int   si[LL];
    int t = threadIdx.x;
    for (int i = t; i < LL; i += 1024) {
        float mm = -CUDART_INF_F, s = 0.f;
#pragma unroll
        for (int c = 0; c < NCHB; c++) {
            mm = fmaxf(mm, g_pM[(c * BH + bh) * LL + i]);
            s += g_pS[(c * BH + bh) * LL + i];
        }
        sv[i] = mm - s * (1.0f / (float)LL);
        si[i] = i;
    }
    __syncthreads();
    for (int k = 2; k <= LL; k <<= 1) {
        for (int j = k >> 1; j > 0; j >>= 1) {
            for (int i = t; i < LL; i += 1024) {
                int p = i ^ j;
                if (p > i) {
                    bool asc = (i & k) == 0;
                    float va = sv[i], vp = sv[p];
                    int   ia = si[i], ip = si[p];
                    bool pre = (vp > va) || (vp == va && ip < ia);
                    if (asc == pre) {
                        sv[i] = vp; sv[p] = va;
                        si[i] = ip; si[p] = ia;
                    }
                }
            }
            __syncthreads();
        }
    }
    if (t < UU) g_Mtop[bh * UU + t] = si[t];
}

// ---------------------------------------------------------------------------
// K4: V_mean partials; 1024 blocks (bh x 32 L-chunks of 64), atomicAdd merge.
// ---------------------------------------------------------------------------
__global__ void k_vmean(const float* __restrict__ V) {
    int blk = blockIdx.x;
    int bh = blk >> 5, chn = blk & 31;
    int b = bh >> 3, h = bh & 7;
    int t = threadIdx.x;
    int d = t & 63, sub = t >> 6;
    float s = 0.f;
#pragma unroll 16
    for (int i = 0; i < 16; i++) {
        int l = chn * 64 + sub + i * 4;
        s += V[(((size_t)(b * LL + l)) * HH + h) * DD + d];
    }
    __shared__ float red[256];
    red[t] = s;
    __syncthreads();
    if (t < 64) {
        float tot = red[t] + red[t + 64] + red[t + 128] + red[t + 192];
        atomicAdd(&g_Vmean[bh * DD + t], tot * (1.0f / (float)LL));
    }
}

// ---------------------------------------------------------------------------
// K5: out[b,l,h,:] = V_mean[b,h,:] for all l.
// ---------------------------------------------------------------------------
__global__ void k_fill(float* __restrict__ out) {
    int i = blockIdx.x * blockDim.x + threadIdx.x;
    if (i >= BB * LL * HH * (DD / 4)) return;
    int q4  = i & 15;
    int row = i >> 4;
    int h = row & 7;
    int b = row >> 14;
    float4 vm = reinterpret_cast<const float4*>(g_Vmean)[((b << 3) + h) * (DD / 4) + q4];
    reinterpret_cast<float4*>(out)[i] = vm;
}

// ---------------------------------------------------------------------------
// K6a: split-K attention partials. Block = (b,h, key-chunk of 128), 256 thr.
// ---------------------------------------------------------------------------
#define QS_PITCH 66
#define KS_PITCH 66
#define S_PITCH  130
#define SH_FLOATS (UU*QS_PITCH + CH*KS_PITCH + CH*KS_PITCH + UU*S_PITCH)
#define SH_BYTES  (SH_FLOATS*4 + UU*4)

__global__ void k_attn_part(const float* __restrict__ Q, const float* __restrict__ K,
                            const float* __restrict__ V) {
    int ch = blockIdx.x & (NCH - 1);
    int bh = blockIdx.x >> 4;
    int b = bh >> 3, h = bh & 7;
    int t = threadIdx.x;

    extern __shared__ float sh[];
    float* Qs = sh;                          // [40][66]
    float* Ks = Qs + UU * QS_PITCH;          // [128][66]
    float* Vs = Ks + CH * KS_PITCH;          // [128][66]
    float* S  = Vs + CH * KS_PITCH;          // [40][130]
    int* sidx = (int*)(S + UU * S_PITCH);    // [40]

    if (t < UU) sidx[t] = g_Mtop[bh * UU + t];
    __syncthreads();

    for (int i = t; i < UU * (DD / 4); i += 256) {
        int j = i >> 4, q4 = i & 15;
        float4 v = *(const float4*)(Q + (((size_t)(b * LL + sidx[j])) * HH + h) * DD + q4 * 4);
        float* dst = Qs + j * QS_PITCH + q4 * 4;
        dst[0] = v.x; dst[1] = v.y; dst[2] = v.z; dst[3] = v.w;
    }
    int k0 = ch * CH;
    for (int i = t; i < CH * (DD / 4); i += 256) {
        int r = i >> 4, q4 = i & 15;
        size_t base = (((size_t)(b * LL + k0 + r)) * HH + h) * DD + q4 * 4;
        float4 kv = *(const float4*)(K + base);
        float4 vv = *(const float4*)(V + base);
        float* dk = Ks + r * KS_PITCH + q4 * 4;
        float* dv = Vs + r * KS_PITCH + q4 * 4;
        dk[0] = kv.x; dk[1] = kv.y; dk[2] = kv.z; dk[3] = kv.w;
        dv[0] = vv.x; dv[1] = vv.y; dv[2] = vv.z; dv[3] = vv.w;
    }
    __syncthreads();

    // ---- phase 1: S[j][k] = scale * dot(Qs[j], Ks[k]) ----
    {
        int kg = t & 31, jg = t >> 5;
        float acc[5][4];
#pragma unroll
        for (int jt = 0; jt < 5; jt++)
#pragma unroll
            for (int kt = 0; kt < 4; kt++) acc[jt][kt] = 0.f;
#pragma unroll 8
        for (int d = 0; d < DD; d++) {
            float qv[5], kv[4];
#pragma unroll
            for (int jt = 0; jt < 5; jt++) qv[jt] = Qs[(jg + 8 * jt) * QS_PITCH + d];
#pragma unroll
            for (int kt = 0; kt < 4; kt++) kv[kt] = Ks[(kg + 32 * kt) * KS_PITCH + d];
#pragma unroll
            for (int jt = 0; jt < 5; jt++)
#pragma unroll
                for (int kt = 0; kt < 4; kt++) acc[jt][kt] += qv[jt] * kv[kt];
        }
#pragma unroll
        for (int jt = 0; jt < 5; jt++)
#pragma unroll
            for (int kt = 0; kt < 4; kt++)
                S[(jg + 8 * jt) * S_PITCH + (kg + 32 * kt)] = acc[jt][kt] * SCALE;
    }
    __syncthreads();

    // ---- phase 2: per-row chunk softmax stats; S <- exp(S - m) ----
    {
        int lane = t & 31, w = t >> 5;
#pragma unroll
        for (int i = 0; i < 5; i++) {
            int j = w * 5 + i;
            float* row = S + j * S_PITCH;
            float v0 = row[lane], v1 = row[lane + 32], v2 = row[lane + 64], v3 = row[lane + 96];
            float m = fmaxf(fmaxf(v0, v1), fmaxf(v2, v3));
            for (int off = 16; off; off >>= 1) m = fmaxf(m, __shfl_xor_sync(0xffffffffu, m, off));
            float e0 = __expf(v0 - m), e1 = __expf(v1 - m);
            float e2 = __expf(v2 - m), e3 = __expf(v3 - m);
            row[lane] = e0; row[lane + 32] = e1; row[lane + 64] = e2; row[lane + 96] = e3;
            float s = e0 + e1 + e2 + e3;
            for (int off = 16; off; off >>= 1) s += __shfl_xor_sync(0xffffffffu, s, off);
            if (lane == 0) {
                g_pm[(bh * UU + j) * NCH + ch] = m;
                g_ps[(bh * UU + j) * NCH + ch] = s;
            }
        }
    }
    __syncthreads();

    // ---- phase 3: partial a[j][d] = sum_k exp * Vs[k][d] (float2 over k) ----
    {
        int d = t & 63, grp = t >> 6;
        float a[10];
#pragma unroll
        for (int jt = 0; jt < 10; jt++) a[jt] = 0.f;
#pragma unroll 2
        for (int k = 0; k < CH; k += 2) {
            float v0 = Vs[k * KS_PITCH + d];
            float v1 = Vs[(k + 1) * KS_PITCH + d];
#pragma unroll
            for (int jt = 0; jt < 10; jt++) {
                float2 sj = *(const float2*)(S + (grp * 10 + jt) * S_PITCH + k);
                a[jt] += sj.x * v0 + sj.y * v1;
            }
        }
#pragma unroll
        for (int jt = 0; jt < 10; jt++)
            g_pa[((bh * UU + grp * 10 + jt) * NCH + ch) * DD + d] = a[jt];
    }
}

// ---------------------------------------------------------------------------
// K6b: merge the 16 chunk partials per (b,h,u); write selected row (over fill).
// ---------------------------------------------------------------------------
__global__ void k_attn_merge(float* __restrict__ out) {
    int u  = blockIdx.x % UU;
    int bh = blockIdx.x / UU;
    int b = bh >> 3, h = bh & 7;
    int d = threadIdx.x;
    int base = (bh * UU + u) * NCH;
    float gm = -CUDART_INF_F;
#pragma unroll
    for (int c = 0; c < NCH; c++) gm = fmaxf(gm, g_pm[base + c]);
    float tot = 0.f, val = 0.f;
#pragma unroll
    for (int c = 0; c < NCH; c++) {
        float e = __expf(g_pm[base + c] - gm);
        tot += g_ps[base + c] * e;
        val += g_pa[(base + c) * DD + d] * e;
    }
    int lq = g_Mtop[bh * UU + u];
    out[(((size_t)(b * LL + lq)) * HH + h) * DD + d] = val / tot;
}

// ---------------------------------------------------------------------------
// Launch: two-branch DAG (fork/join via events; capture-legal, alloc-free).
// ---------------------------------------------------------------------------
extern "C" void kernel_launch(void* const* d_in, const int* in_sizes, int n_in,
                              void* d_out, int out_size) {
    const float* Q = (const float*)d_in[0];
    const float* K = (const float*)d_in[1];
    const float* V = (const float*)d_in[2];
    float* out = (float*)d_out;

    static cudaStream_t s2 = nullptr;
    static cudaEvent_t evFork = nullptr, evJoin = nullptr;
    if (s2 == nullptr) {
        cudaStreamCreateWithFlags(&s2, cudaStreamNonBlocking);
        cudaEventCreateWithFlags(&evFork, cudaEventDisableTiming);
        cudaEventCreateWithFlags(&evJoin, cudaEventDisableTiming);
        cudaFuncSetAttribute(k_attn_part, cudaFuncAttributeMaxDynamicSharedMemorySize,
                             SH_BYTES);
        cudaFuncSetAttribute(k_sampleM7, cudaFuncAttributeMaxDynamicSharedMemorySize,
                             SMP_SH_BYTES);
    }

    // fork side branch (depends only on V / device globals)
    cudaEventRecord(evFork, 0);
    cudaStreamWaitEvent(s2, evFork, 0);
    k_zero<<<(BH * DD) / 1024, 1024, 0, s2>>>();
    k_vmean<<<BH * 32, 256, 0, s2>>>(V);
    k_fill<<<(BB * LL * HH * (DD / 4)) / 256, 256, 0, s2>>>(out);
    cudaEventRecord(evJoin, s2);

    // critical path
    k_prep<<<LL / 8, 256>>>();
    k_sampleM7<<<BH * NCHB, 1024, SMP_SH_BYTES>>>(Q, K);
    k_topk<<<BH, 1024>>>();
    k_attn_part<<<BH * NCH, 256, SH_BYTES>>>(Q, K, V);

    // join: attn_merge needs fill's output in place
    cudaStreamWaitEvent(0, evJoin, 0);
    k_attn_merge<<<BH * UU, DD>>>(out);
}

// round 17
// speedup vs baseline: 1.0772x; 1.0219x over previous
#include <cuda_runtime.h>
#include <stdint.h>
#include <math_constants.h>

// ProbSparse attention (Informer) — B=4, L=2048, H=8, D=64, U_part=u=40.
// Layout of all tensors: (B, L, H, D) row-major.

#define BB 4
#define LL 2048
#define HH 8
#define DD 64
#define UU 40
#define SS 40
#define BH (BB*HH)       // 32
#define NCHB 4           // key chunks for sampled-score bucketing
#define CKEY 512         // keys per bucket chunk
#define CSH  9           // log2(CKEY)
#define NCH 16           // key chunks for split-K attention
#define CH  128
#define SCALE 0.125f

__device__ __align__(16) uint16_t g_cnt16[NCHB*LL];
__device__ __align__(16) uint16_t g_pairs2[NCHB*LL*SS];   // [c][l][<=40]
__device__ __align__(16) float    g_pM[NCHB*BH*LL];
__device__ __align__(16) float    g_pS[NCHB*BH*LL];
__device__ __align__(16) int      g_Mtop[BH*UU];
__device__ __align__(16) float    g_Vmean[BH*DD];
__device__ __align__(16) float    g_pm[BH*UU*NCH];
__device__ __align__(16) float    g_ps[BH*UU*NCH];
__device__ __align__(16) float    g_pa[BH*UU*NCH*DD];

// ---------------------------------------------------------------------------
// Threefry-2x32-20, constexpr-evaluable.
// ---------------------------------------------------------------------------
__host__ __device__ constexpr uint64_t tf2x32(uint32_t k0, uint32_t k1,
                                              uint32_t c0, uint32_t c1) {
    uint32_t ks0 = k0, ks1 = k1, ks2 = k0 ^ k1 ^ 0x1BD11BDAu;
    uint32_t x0 = c0 + ks0, x1 = c1 + ks1;
    const int rotA[4] = {13, 15, 26, 6};
    const int rotB[4] = {17, 29, 16, 24};
    for (int g = 0; g < 5; g++) {
        const int* rot = (g & 1) ? rotB : rotA;
        for (int r = 0; r < 4; r++) {
            x0 += x1;
            x1 = (x1 << rot[r]) | (x1 >> (32 - rot[r]));
            x1 ^= x0;
        }
        uint32_t inj0 = 0, inj1 = 0;
        switch (g) {
            case 0: inj0 = ks1; inj1 = ks2 + 1u; break;
            case 1: inj0 = ks2; inj1 = ks0 + 2u; break;
            case 2: inj0 = ks0; inj1 = ks1 + 3u; break;
            case 3: inj0 = ks1; inj1 = ks2 + 4u; break;
            case 4: inj0 = ks2; inj1 = ks0 + 5u; break;
        }
        x0 += inj0; x1 += inj1;
    }
    return ((uint64_t)x0 << 32) | (uint64_t)x1;
}

constexpr uint64_t K2PAIR = tf2x32(0u, 42u, 0u, 1u);
#define K2_HI ((uint32_t)(K2PAIR >> 32))
#define K2_LO ((uint32_t)(K2PAIR & 0xffffffffu))

// ---------------------------------------------------------------------------
// K0 (side stream): zero g_Vmean.
// ---------------------------------------------------------------------------
__global__ void k_zero() {
    int i = blockIdx.x * 1024 + threadIdx.x;
    g_Vmean[i] = 0.f;
}

// ---------------------------------------------------------------------------
// K1: warp-parallel rng+count+rank (ballot/popc stable scatter).
// ---------------------------------------------------------------------------
__device__ __forceinline__ uint32_t tf_fold(uint32_t c1v) {
    uint64_t y = tf2x32(K2_HI, K2_LO, 0u, c1v);
    return (uint32_t)(y >> 32) ^ (uint32_t)(y & 0xffffffffu);
}

__global__ void k_prep() {
    int lane = threadIdx.x & 31;
    int l = blockIdx.x * 8 + (threadIdx.x >> 5);

    int idx1 = (int)(tf_fold((uint32_t)(l * SS + lane)) & (LL - 1));
    int idx2 = 0;
    if (lane < 8)
        idx2 = (int)(tf_fold((uint32_t)(l * SS + 32 + lane)) & (LL - 1));

    int c1 = idx1 >> CSH;
    int c2 = (lane < 8) ? (idx2 >> CSH) : -1;

    uint32_t m1[NCHB], m2[NCHB];
#pragma unroll
    for (int c = 0; c < NCHB; c++) {
        m1[c] = __ballot_sync(0xffffffffu, c1 == c);
        m2[c] = __ballot_sync(0xffffffffu, c2 == c);
    }
    uint32_t ltmask = (1u << lane) - 1u;

    uint32_t mm1 = (c1 == 0) ? m1[0] : (c1 == 1) ? m1[1] : (c1 == 2) ? m1[2] : m1[3];
    int r1 = __popc(mm1 & ltmask);
    g_pairs2[(c1 * LL + l) * SS + r1] = (uint16_t)(idx1 & (CKEY - 1));

    if (lane < 8) {
        uint32_t mm1b = (c2 == 0) ? m1[0] : (c2 == 1) ? m1[1] : (c2 == 2) ? m1[2] : m1[3];
        uint32_t mm2  = (c2 == 0) ? m2[0] : (c2 == 1) ? m2[1] : (c2 == 2) ? m2[2] : m2[3];
        int r2 = __popc(mm1b) + __popc(mm2 & ltmask);
        g_pairs2[(c2 * LL + l) * SS + r2] = (uint16_t)(idx2 & (CKEY - 1));
    }

    if (lane < NCHB)
        g_cnt16[lane * LL + l] = (uint16_t)(__popc(m1[lane]) + __popc(m2[lane]));
}

// ---------------------------------------------------------------------------
// K2: sampled-score partials — dual-query warps, predicated tail loads.
// ---------------------------------------------------------------------------
#define SMP_SH_BYTES (CKEY*DD*4 + LL*2)

__global__ void __launch_bounds__(1024, 1) k_sampleM7(const float* __restrict__ Q,
                                                      const float* __restrict__ K) {
    int c  = blockIdx.x & (NCHB - 1);
    int bh = blockIdx.x >> 2;
    int b = bh >> 3, h = bh & 7;

    extern __shared__ float sk[];                    // [512][64]
    uint16_t* scnt = (uint16_t*)(sk + CKEY * DD);    // [2048]

    const float* Kc = K + ((size_t)(b * LL + c * CKEY) * HH + h) * DD;
    for (int i = threadIdx.x; i < CKEY * (DD / 4); i += 1024) {
        int r = i >> 4, q4 = i & 15;
        float4 v = __ldcg((const float4*)(Kc + (size_t)r * (HH * DD) + q4 * 4));
        *(float4*)(sk + r * DD + q4 * 4) = v;
    }
    for (int i = threadIdx.x; i < LL; i += 1024)
        scnt[i] = g_cnt16[c * LL + i];
    __syncthreads();

    int lane = threadIdx.x & 31, wid = threadIdx.x >> 5;
    int oct = lane >> 3;           // sample slot 0..3
    int oj4 = (lane & 7) * 4;      // float offset within 128B segment

    for (int l = wid; l < LL / 2; l += 32) {
        int lA = l, lB = l + LL / 2;
        int cntA = (int)scnt[lA];
        int cntB = (int)scnt[lB];

        const float* qrA = Q + ((size_t)(b * LL + lA) * HH + h) * DD;
        const float* qrB = Q + ((size_t)(b * LL + lB) * HH + h) * DD;
        float4 qaA = __ldcg((const float4*)(qrA + oj4));
        float4 qbA = __ldcg((const float4*)(qrA + 32 + oj4));
        float4 qaB = __ldcg((const float4*)(qrB + oj4));
        float4 qbB = __ldcg((const float4*)(qrB + 32 + oj4));

        const uint16_t* prA = g_pairs2 + (c * LL + lA) * SS;
        const uint16_t* prB = g_pairs2 + (c * LL + lB) * SS;
        int paA = (lane < cntA) ? (int)prA[lane] : 0;
        int paB = (lane < cntB) ? (int)prB[lane] : 0;

        float mxA = -CUDART_INF_F, smA = 0.f;
        float mxB = -CUDART_INF_F, smB = 0.f;

        int mc = max(cntA, cntB);
        int lim = min(mc, 32);
        for (int t0 = 0; t0 < lim; t0 += 4) {
            int srcl = (t0 + oct) & 31;
            int kA = __shfl_sync(0xffffffffu, paA, srcl);
            int kB = __shfl_sync(0xffffffffu, paB, srcl);
            bool vA = (t0 + oct) < cntA;
            bool vB = (t0 + oct) < cntB;
            float pA = 0.f, pB = 0.f;
            if (vA) {   // predicated: tail octets issue no LDS wavefronts
                const float* ra = sk + kA * DD;
                float4 kaA = *(const float4*)(ra + oj4);
                float4 kbA = *(const float4*)(ra + 32 + oj4);
                pA = qaA.x * kaA.x + qaA.y * kaA.y + qaA.z * kaA.z + qaA.w * kaA.w
                   + qbA.x * kbA.x + qbA.y * kbA.y + qbA.z * kbA.z + qbA.w * kbA.w;
            }
            if (vB) {
                const float* rb = sk + kB * DD;
                float4 kaB = *(const float4*)(rb + oj4);
                float4 kbB = *(const float4*)(rb + 32 + oj4);
                pB = qaB.x * kaB.x + qaB.y * kaB.y + qaB.z * kaB.z + qaB.w * kaB.w
                   + qbB.x * kbB.x + qbB.y * kbB.y + qbB.z * kbB.z + qbB.w * kbB.w;
            }
            pA += __shfl_xor_sync(0xffffffffu, pA, 1);
            pB += __shfl_xor_sync(0xffffffffu, pB, 1);
            pA += __shfl_xor_sync(0xffffffffu, pA, 2);
            pB += __shfl_xor_sync(0xffffffffu, pB, 2);
            pA += __shfl_xor_sync(0xffffffffu, pA, 4);
            pB += __shfl_xor_sync(0xffffffffu, pB, 4);
            if (vA) { mxA = fmaxf(mxA, pA); smA += pA; }
            if (vB) { mxB = fmaxf(mxB, pB); smB += pB; }
        }
        if (cntA > 32) {
            int pbA = (lane + 32 < cntA) ? (int)prA[lane + 32] : 0;
            for (int t0 = 32; t0 < cntA; t0 += 4) {
                int kA = __shfl_sync(0xffffffffu, pbA, (t0 - 32) + oct);
                const float* ra = sk + kA * DD;
                float4 kaA = *(const float4*)(ra + oj4);
                float4 kbA = *(const float4*)(ra + 32 + oj4);
                float pA = qaA.x * kaA.x + qaA.y * kaA.y + qaA.z * kaA.z + qaA.w * kaA.w
                         + qbA.x * kbA.x + qbA.y * kbA.y + qbA.z * kbA.z + qbA.w * kbA.w;
                pA += __shfl_xor_sync(0xffffffffu, pA, 1);
                pA += __shfl_xor_sync(0xffffffffu, pA, 2);
                pA += __shfl_xor_sync(0xffffffffu, pA, 4);
                if (t0 + oct < cntA) { mxA = fmaxf(mxA, pA); smA += pA; }
            }
        }
        if (cntB > 32) {
            int pbB = (lane + 32 < cntB) ? (int)prB[lane + 32] : 0;
            for (int t0 = 32; t0 < cntB; t0 += 4) {
                int kB = __shfl_sync(0xffffffffu, pbB, (t0 - 32) + oct);
                const float* rb = sk + kB * DD;
                float4 kaB = *(const float4*)(rb + oj4);
                float4 kbB = *(const float4*)(rb + 32 + oj4);
                float pB = qaB.x * kaB.x + qaB.y * kaB.y + qaB.z * kaB.z + qaB.w * kaB.w
                         + qbB.x * kbB.x + qbB.y * kbB.y + qbB.z * kbB.z + qbB.w * kbB.w;
                pB += __shfl_xor_sync(0xffffffffu, pB, 1);
                pB += __shfl_xor_sync(0xffffffffu, pB, 2);
                pB += __shfl_xor_sync(0xffffffffu, pB, 4);
                if (t0 + oct < cntB) { mxB = fmaxf(mxB, pB); smB += pB; }
            }
        }
        mxA = fmaxf(mxA, __shfl_xor_sync(0xffffffffu, mxA, 8));
        mxB = fmaxf(mxB, __shfl_xor_sync(0xffffffffu, mxB, 8));
        mxA = fmaxf(mxA, __shfl_xor_sync(0xffffffffu, mxA, 16));
        mxB = fmaxf(mxB, __shfl_xor_sync(0xffffffffu, mxB, 16));
        smA += __shfl_xor_sync(0xffffffffu, smA, 8);
        smB += __shfl_xor_sync(0xffffffffu, smB, 8);
        smA += __shfl_xor_sync(0xffffffffu, smA, 16);
        smB += __shfl_xor_sync(0xffffffffu, smB, 16);
        if (lane == 0) {
            g_pM[(c * BH + bh) * LL + lA] = mxA;
            g_pS[(c * BH + bh) * LL + lA] = smA;
            g_pM[(c * BH + bh) * LL + lB] = mxB;
            g_pS[(c * BH + bh) * LL + lB] = smB;
        }
    }
}

// ---------------------------------------------------------------------------
// K3: merge 4 chunk partials -> M, then exact top-40 per (b,h).
// uint64 keys: (monotonic(v) << 32) | (0xFFFFFFFF - idx), bitonic sort
// DESCENDING -> exactly (v desc, idx asc). 1024 threads.
// ---------------------------------------------------------------------------
__global__ void k_topk() {
    int bh = blockIdx.x;
    __shared__ uint64_t sv[LL];
    int t = threadIdx.x;
    for (int i = t; i < LL; i += 1024) {
        float mm = -CUDART_INF_F, s = 0.f;
#pragma unroll
        for (int c = 0; c < NCHB; c++) {
            mm = fmaxf(mm, g_pM[(c * BH + bh) * LL + i]);
            s += g_pS[(c * BH + bh) * LL + i];
        }
        float M = mm - s * (1.0f / (float)LL);
        uint32_t b32 = __float_as_uint(M);
        uint32_t mono = b32 ^ (((int32_t)b32 >> 31) | 0x80000000u);  // asc-ordered
        sv[i] = ((uint64_t)mono << 32) | (uint64_t)(0xFFFFFFFFu - (uint32_t)i);
    }
    __syncthreads();
    for (int k = 2; k <= LL; k <<= 1) {
        for (int j = k >> 1; j > 0; j >>= 1) {
            for (int i = t; i < LL; i += 1024) {
                int p = i ^ j;
                if (p > i) {
                    bool desc = (i & k) == 0;          // descending regions
                    uint64_t a = sv[i], bb = sv[p];
                    bool swap = desc ? (bb > a) : (bb < a);
                    if (swap) { sv[i] = bb; sv[p] = a; }
                }
            }
            __syncthreads();
        }
    }
    if (t < UU)
        g_Mtop[bh * UU + t] = (int)(0xFFFFFFFFu - (uint32_t)(sv[t] & 0xFFFFFFFFu));
}

// ---------------------------------------------------------------------------
// K4: V_mean partials; 1024 blocks (bh x 32 L-chunks of 64), atomicAdd merge.
// ---------------------------------------------------------------------------
__global__ void k_vmean(const float* __restrict__ V) {
    int blk = blockIdx.x;
    int bh = blk >> 5, chn = blk & 31;
    int b = bh >> 3, h = bh & 7;
    int t = threadIdx.x;
    int d = t & 63, sub = t >> 6;
    float s = 0.f;
#pragma unroll 16
    for (int i = 0; i < 16; i++) {
        int l = chn * 64 + sub + i * 4;
        s += V[(((size_t)(b * LL + l)) * HH + h) * DD + d];
    }
    __shared__ float red[256];
    red[t] = s;
    __syncthreads();
    if (t < 64) {
        float tot = red[t] + red[t + 64] + red[t + 128] + red[t + 192];
        atomicAdd(&g_Vmean[bh * DD + t], tot * (1.0f / (float)LL));
    }
}

// ---------------------------------------------------------------------------
// K5: out[b,l,h,:] = V_mean[b,h,:] for all l.
// ---------------------------------------------------------------------------
__global__ void k_fill(float* __restrict__ out) {
    int i = blockIdx.x * blockDim.x + threadIdx.x;
    if (i >= BB * LL * HH * (DD / 4)) return;
    int q4  = i & 15;
    int row = i >> 4;
    int h = row & 7;
    int b = row >> 14;
    float4 vm = reinterpret_cast<const float4*>(g_Vmean)[((b << 3) + h) * (DD / 4) + q4];
    reinterpret_cast<float4*>(out)[i] = vm;
}

// ---------------------------------------------------------------------------
// K6a: split-K attention partials. Block = (b,h, key-chunk of 128), 512 thr.
// Phase 1: 16 warps, per-thread 5x2 tile (k split in halves).
// Phase 2: 16 warps stride 40 rows. Phase 3: 8 d-groups x 5 rows.
// ---------------------------------------------------------------------------
#define QS_PITCH 66
#define KS_PITCH 66
#define S_PITCH  130
#define SH_FLOATS (UU*QS_PITCH + CH*KS_PITCH + CH*KS_PITCH + UU*S_PITCH)
#define SH_BYTES  (SH_FLOATS*4 + UU*4)

__global__ void __launch_bounds__(512) k_attn_part(const float* __restrict__ Q,
                                                   const float* __restrict__ K,
                                                   const float* __restrict__ V) {
    int ch = blockIdx.x & (NCH - 1);
    int bh = blockIdx.x >> 4;
    int b = bh >> 3, h = bh & 7;
    int t = threadIdx.x;

    extern __shared__ float sh[];
    float* Qs = sh;                          // [40][66]
    float* Ks = Qs + UU * QS_PITCH;          // [128][66]
    float* Vs = Ks + CH * KS_PITCH;          // [128][66]
    float* S  = Vs + CH * KS_PITCH;          // [40][130]
    int* sidx = (int*)(S + UU * S_PITCH);    // [40]

    if (t < UU) sidx[t] = g_Mtop[bh * UU + t];
    __syncthreads();

    for (int i = t; i < UU * (DD / 4); i += 512) {
        int j = i >> 4, q4 = i & 15;
        float4 v = *(const float4*)(Q + (((size_t)(b * LL + sidx[j])) * HH + h) * DD + q4 * 4);
        float* dst = Qs + j * QS_PITCH + q4 * 4;
        dst[0] = v.x; dst[1] = v.y; dst[2] = v.z; dst[3] = v.w;
    }
    int k0 = ch * CH;
    for (int i = t; i < CH * (DD / 4); i += 512) {
        int r = i >> 4, q4 = i & 15;
        size_t base = (((size_t)(b * LL + k0 + r)) * HH + h) * DD + q4 * 4;
        float4 kv = *(const float4*)(K + base);
        float4 vv = *(const float4*)(V + base);
        float* dk = Ks + r * KS_PITCH + q4 * 4;
        float* dv = Vs + r * KS_PITCH + q4 * 4;
        dk[0] = kv.x; dk[1] = kv.y; dk[2] = kv.z; dk[3] = kv.w;
        dv[0] = vv.x; dv[1] = vv.y; dv[2] = vv.z; dv[3] = vv.w;
    }
    __syncthreads();

    // ---- phase 1: S[j][k] = scale * dot(Qs[j], Ks[k]); 5x2 tiles ----
    {
        int lane = t & 31;
        int jg = (t >> 5) & 7;       // 8 row-groups
        int kh = t >> 8;             // k-half 0/1
        float acc[5][2];
#pragma unroll
        for (int jt = 0; jt < 5; jt++) { acc[jt][0] = 0.f; acc[jt][1] = 0.f; }
#pragma unroll 8
        for (int d = 0; d < DD; d++) {
            float qv[5], kv[2];
#pragma unroll
            for (int jt = 0; jt < 5; jt++) qv[jt] = Qs[(jg + 8 * jt) * QS_PITCH + d];
            kv[0] = Ks[(kh * 64 + lane) * KS_PITCH + d];
            kv[1] = Ks[(kh * 64 + lane + 32) * KS_PITCH + d];
#pragma unroll
            for (int jt = 0; jt < 5; jt++) {
                acc[jt][0] += qv[jt] * kv[0];
                acc[jt][1] += qv[jt] * kv[1];
            }
        }
#pragma unroll
        for (int jt = 0; jt < 5; jt++) {
            S[(jg + 8 * jt) * S_PITCH + kh * 64 + lane]      = acc[jt][0] * SCALE;
            S[(jg + 8 * jt) * S_PITCH + kh * 64 + lane + 32] = acc[jt][1] * SCALE;
        }
    }
    __syncthreads();

    // ---- phase 2: per-row chunk softmax stats; S <- exp(S - m) ----
    {
        int lane = t & 31, w = t >> 5;     // 16 warps
        for (int j = w; j < UU; j += 16) {
            float* row = S + j * S_PITCH;
            float v0 = row[lane], v1 = row[lane + 32], v2 = row[lane + 64], v3 = row[lane + 96];
            float m = fmaxf(fmaxf(v0, v1), fmaxf(v2, v3));
            for (int off = 16; off; off >>= 1) m = fmaxf(m, __shfl_xor_sync(0xffffffffu, m, off));
            float e0 = __expf(v0 - m), e1 = __expf(v1 - m);
            float e2 = __expf(v2 - m), e3 = __expf(v3 - m);
            row[lane] = e0; row[lane + 32] = e1; row[lane + 64] = e2; row[lane + 96] = e3;
            float s = e0 + e1 + e2 + e3;
            for (int off = 16; off; off >>= 1) s += __shfl_xor_sync(0xffffffffu, s, off);
            if (lane == 0) {
                g_pm[(bh * UU + j) * NCH + ch] = m;
                g_ps[(bh * UU + j) * NCH + ch] = s;
            }
        }
    }
    __syncthreads();

    // ---- phase 3: partial a[j][d] = sum_k exp * Vs[k][d]; 8 groups x 5 rows ----
    {
        int d = t & 63, grp = t >> 6;      // 8 groups
        float a[5];
#pragma unroll
        for (int jt = 0; jt < 5; jt++) a[jt] = 0.f;
#pragma unroll 2
        for (int k = 0; k < CH; k += 2) {
            float v0 = Vs[k * KS_PITCH + d];
            float v1 = Vs[(k + 1) * KS_PITCH + d];
#pragma unroll
            for (int jt = 0; jt < 5; jt++) {
                float2 sj = *(const float2*)(S + (grp * 5 + jt) * S_PITCH + k);
                a[jt] += sj.x * v0 + sj.y * v1;
            }
        }
#pragma unroll
        for (int jt = 0; jt < 5; jt++)
            g_pa[((bh * UU + grp * 5 + jt) * NCH + ch) * DD + d] = a[jt];
    }
}

// ---------------------------------------------------------------------------
// K6b: merge the 16 chunk partials per (b,h,u); write selected row (over fill).
// ---------------------------------------------------------------------------
__global__ void k_attn_merge(float* __restrict__ out) {
    int u  = blockIdx.x % UU;
    int bh = blockIdx.x / UU;
    int b = bh >> 3, h = bh & 7;
    int d = threadIdx.x;
    int base = (bh * UU + u) * NCH;
    float gm = -CUDART_INF_F;
#pragma unroll
    for (int c = 0; c < NCH; c++) gm = fmaxf(gm, g_pm[base + c]);
    float tot = 0.f, val = 0.f;
#pragma unroll
    for (int c = 0; c < NCH; c++) {
        float e = __expf(g_pm[base + c] - gm);
        tot += g_ps[base + c] * e;
        val += g_pa[(base + c) * DD + d] * e;
    }
    int lq = g_Mtop[bh * UU + u];
    out[(((size_t)(b * LL + lq)) * HH + h) * DD + d] = val / tot;
}

// ---------------------------------------------------------------------------
// Launch: two-branch DAG (fork/join via events; capture-legal, alloc-free).
// ---------------------------------------------------------------------------
extern "C" void kernel_launch(void* const* d_in, const int* in_sizes, int n_in,
                              void* d_out, int out_size) {
    const float* Q = (const float*)d_in[0];
    const float* K = (const float*)d_in[1];
    const float* V = (const float*)d_in[2];
    float* out = (float*)d_out;

    static cudaStream_t s2 = nullptr;
    static cudaEvent_t evFork = nullptr, evJoin = nullptr;
    if (s2 == nullptr) {
        cudaStreamCreateWithFlags(&s2, cudaStreamNonBlocking);
        cudaEventCreateWithFlags(&evFork, cudaEventDisableTiming);
        cudaEventCreateWithFlags(&evJoin, cudaEventDisableTiming);
        cudaFuncSetAttribute(k_attn_part, cudaFuncAttributeMaxDynamicSharedMemorySize,
                             SH_BYTES);
        cudaFuncSetAttribute(k_sampleM7, cudaFuncAttributeMaxDynamicSharedMemorySize,
                             SMP_SH_BYTES);
    }

    // fork side branch (depends only on V / device globals)
    cudaEventRecord(evFork, 0);
    cudaStreamWaitEvent(s2, evFork, 0);
    k_zero<<<(BH * DD) / 1024, 1024, 0, s2>>>();
    k_vmean<<<BH * 32, 256, 0, s2>>>(V);
    k_fill<<<(BB * LL * HH * (DD / 4)) / 256, 256, 0, s2>>>(out);
    cudaEventRecord(evJoin, s2);

    // critical path
    k_prep<<<LL / 8, 256>>>();
    k_sampleM7<<<BH * NCHB, 1024, SMP_SH_BYTES>>>(Q, K);
    k_topk<<<BH, 1024>>>();
    k_attn_part<<<BH * NCH, 512, SH_BYTES>>>(Q, K, V);

    // join: attn_merge needs fill's output in place
    cudaStreamWaitEvent(0, evJoin, 0);
    k_attn_merge<<<BH * UU, DD>>>(out);
}